// round 1
// baseline (speedup 1.0000x reference)
#include <cuda_runtime.h>

#define NN 2048
#define KK 16
#define FF 256
#define OO 256

// ---- scratch (static device memory; no allocation) ----
__device__ unsigned int g_mask[NN];
__device__ int   g_list[KK * NN];
__device__ int   g_cnt[KK];
__device__ float g_h[NN * OO];
__device__ float g_colsum[OO];
__device__ float g_colsumsq[OO];

// ---------------------------------------------------------------
// 0) zero scratch + coarsen region of output
// ---------------------------------------------------------------
__global__ void zero_kernel(float* __restrict__ out_tail) {
    int idx = blockIdx.x * blockDim.x + threadIdx.x;
    if (idx < NN * OO) g_h[idx] = 0.f;
    if (idx < OO) { g_colsum[idx] = 0.f; g_colsumsq[idx] = 0.f; }
    if (idx < KK * KK) out_tail[idx] = 0.f;
}

// ---------------------------------------------------------------
// 1) per-node hard assignment mask: relu(x@W+b) == rowmax (ties kept)
//    one warp per node
// ---------------------------------------------------------------
__global__ void assign_kernel(const float* __restrict__ x,
                              const float* __restrict__ w,
                              const float* __restrict__ b) {
    int node = (blockIdx.x * blockDim.x + threadIdx.x) >> 5;
    int lane = threadIdx.x & 31;
    if (node >= NN) return;
    float p[KK];
#pragma unroll
    for (int k = 0; k < KK; k++) p[k] = 0.f;
    const float* xr = x + node * FF;
    for (int f = lane; f < FF; f += 32) {
        float xv = xr[f];
        const float* wr = w + f * KK;
#pragma unroll
        for (int k = 0; k < KK; k++) p[k] += xv * wr[k];
    }
#pragma unroll
    for (int k = 0; k < KK; k++) {
#pragma unroll
        for (int off = 16; off >= 1; off >>= 1)
            p[k] += __shfl_xor_sync(0xffffffffu, p[k], off);
    }
    if (lane == 0) {
        float m = 0.f;
#pragma unroll
        for (int k = 0; k < KK; k++) {
            p[k] = fmaxf(p[k] + b[k], 0.f);
            m = fmaxf(m, p[k]);
        }
        unsigned mask = 0u;
#pragma unroll
        for (int k = 0; k < KK; k++)
            if (p[k] == m) mask |= (1u << k);
        g_mask[node] = mask;
    }
}

// ---------------------------------------------------------------
// 2) deterministic compacted member lists per group (single warp scan)
// ---------------------------------------------------------------
__global__ void build_lists_kernel() {
    int lane = threadIdx.x;
    int cnt[KK];
#pragma unroll
    for (int k = 0; k < KK; k++) cnt[k] = 0;
    for (int base = 0; base < NN; base += 32) {
        unsigned m = g_mask[base + lane];
#pragma unroll
        for (int k = 0; k < KK; k++) {
            unsigned bal = __ballot_sync(0xffffffffu, (m >> k) & 1u);
            if ((m >> k) & 1u)
                g_list[k * NN + cnt[k] + __popc(bal & ((1u << lane) - 1u))] = base + lane;
            cnt[k] += __popc(bal);
        }
    }
    if (lane < KK) g_cnt[lane] = cnt[lane];
}

// ---------------------------------------------------------------
// 3) coarsen_adj[a][b] = sum_{i in a, j in b} adj[i][j]
//    one warp per row i, bit-unrolled accumulators, shfl reduce
// ---------------------------------------------------------------
__global__ void coarsen_kernel(const float* __restrict__ adj,
                               float* __restrict__ out_tail) {
    __shared__ unsigned mask_sh[NN];
    for (int i = threadIdx.x; i < NN; i += blockDim.x) mask_sh[i] = g_mask[i];
    __syncthreads();
    int w = threadIdx.x >> 5, lane = threadIdx.x & 31;
    int i = blockIdx.x * 8 + w;
    float c[KK];
#pragma unroll
    for (int k = 0; k < KK; k++) c[k] = 0.f;
    const float* arow = adj + (size_t)i * NN;
    for (int j = lane; j < NN; j += 32) {
        float a = arow[j];
        unsigned m = mask_sh[j];
#pragma unroll
        for (int k = 0; k < KK; k++)
            if (m & (1u << k)) c[k] += a;
    }
#pragma unroll
    for (int k = 0; k < KK; k++) {
#pragma unroll
        for (int off = 16; off >= 1; off >>= 1)
            c[k] += __shfl_xor_sync(0xffffffffu, c[k], off);
    }
    if (lane == 0) {
        unsigned mi = mask_sh[i];
#pragma unroll
        for (int bcol = 0; bcol < KK; bcol++) {
            unsigned mm = mi;
            while (mm) {
                int a = __ffs(mm) - 1;
                mm &= mm - 1;
                atomicAdd(&out_tail[a * KK + bcol], c[bcol]);
            }
        }
    }
}

// ---------------------------------------------------------------
// 4) GCN per-group: tile of 16 member nodes per block.
//    V = A_sub @ X_sub + 2*X ; Z = V @ W_k ; L2-normalize rows; add into h.
// ---------------------------------------------------------------
__global__ void __launch_bounds__(256) gcn_kernel(const float* __restrict__ x,
                                                  const float* __restrict__ adj,
                                                  const float* __restrict__ gw) {
    int k = blockIdx.y;
    int n = g_cnt[k];
    int t0 = blockIdx.x * 16;
    if (t0 >= n) return;

    __shared__ int   list_sh[NN];
    __shared__ float a_sh[16][65];
    __shared__ float v_sh[16][260];
    __shared__ float red_sh[16][8];
    __shared__ float inv_sh[16];

    int tid = threadIdx.x;
    for (int i = tid; i < n; i += 256) list_sh[i] = g_list[k * NN + i];
    __syncthreads();

    int rows = n - t0; if (rows > 16) rows = 16;
    int irow[16];
#pragma unroll
    for (int r = 0; r < 16; r++) irow[r] = list_sh[t0 + (r < rows ? r : 0)];

    const int f = tid;  // feature / output column index, 0..255
    float acc[16];
#pragma unroll
    for (int r = 0; r < 16; r++) acc[r] = 2.f * x[(size_t)irow[r] * FF + f];

    // stage 1: acc[r] += sum_{j in group} adj[irow[r], j] * x[j, f]
    for (int j0 = 0; j0 < n; j0 += 64) {
        int cmax = n - j0; if (cmax > 64) cmax = 64;
        for (int e = tid; e < 16 * 64; e += 256) {
            int r = e >> 6, c = e & 63;
            float a = 0.f;
            if (c < cmax) {
                int rr = (r < rows) ? r : 0;
                a = adj[(size_t)list_sh[t0 + rr] * NN + list_sh[j0 + c]];
            }
            a_sh[r][c] = a;
        }
        __syncthreads();
        for (int c = 0; c < cmax; c++) {
            float xv = x[(size_t)list_sh[j0 + c] * FF + f];
#pragma unroll
            for (int r = 0; r < 16; r++) acc[r] += a_sh[r][c] * xv;
        }
        __syncthreads();
    }

#pragma unroll
    for (int r = 0; r < 16; r++) v_sh[r][f] = acc[r];
    __syncthreads();

    // stage 2: Z[r][f] = sum_ff V[r][ff] * W_k[ff][f]   (coalesced W reads)
    float z[16];
#pragma unroll
    for (int r = 0; r < 16; r++) z[r] = 0.f;
    const float* Wk = gw + (size_t)k * FF * OO + f;
    for (int ff = 0; ff < FF; ff++) {
        float wv = Wk[(size_t)ff * OO];
#pragma unroll
        for (int r = 0; r < 16; r++) z[r] += v_sh[r][ff] * wv;
    }

    // per-row L2 norm across the 256 threads
    int lane = tid & 31, wrp = tid >> 5;
#pragma unroll
    for (int r = 0; r < 16; r++) {
        float v = z[r] * z[r];
#pragma unroll
        for (int off = 16; off >= 1; off >>= 1)
            v += __shfl_xor_sync(0xffffffffu, v, off);
        if (lane == 0) red_sh[r][wrp] = v;
    }
    __syncthreads();
    if (tid < 16) {
        float s = 0.f;
#pragma unroll
        for (int ww = 0; ww < 8; ww++) s += red_sh[tid][ww];
        inv_sh[tid] = 1.f / fmaxf(sqrtf(s), 1e-12f);
    }
    __syncthreads();

#pragma unroll
    for (int r = 0; r < 16; r++)
        if (r < rows)
            atomicAdd(&g_h[(size_t)irow[r] * OO + f], z[r] * inv_sh[r]);
}

// ---------------------------------------------------------------
// 5) BN column statistics over relu(h)
// ---------------------------------------------------------------
__global__ void bn_stats_kernel() {
    int o = threadIdx.x;
    int r0 = blockIdx.x * 32;
    float s = 0.f, s2 = 0.f;
    for (int r = 0; r < 32; r++) {
        float v = fmaxf(g_h[(size_t)(r0 + r) * OO + o], 0.f);
        s += v; s2 += v * v;
    }
    atomicAdd(&g_colsum[o], s);
    atomicAdd(&g_colsumsq[o], s2);
}

// ---------------------------------------------------------------
// 6) apply BN and pool: out[a][o] = sum_{i in group a} h_bn[i][o]
// ---------------------------------------------------------------
__global__ void final_kernel(float* __restrict__ out) {
    int a = blockIdx.x;
    int o = threadIdx.x;
    const float invN = 1.f / (float)NN;
    float mean = g_colsum[o] * invN;
    float var  = g_colsumsq[o] * invN - mean * mean;
    float inv  = 1.f / sqrtf(var + 1e-5f);
    int n = g_cnt[a];
    float accv = 0.f;
    for (int t = 0; t < n; t++) {
        int i = g_list[a * NN + t];
        float v = fmaxf(g_h[(size_t)i * OO + o], 0.f);
        accv += (v - mean) * inv;
    }
    out[a * OO + o] = accv;
}

// ---------------------------------------------------------------
extern "C" void kernel_launch(void* const* d_in, const int* in_sizes, int n_in,
                              void* d_out, int out_size) {
    const float* x      = (const float*)d_in[0];
    const float* adj    = (const float*)d_in[1];
    const float* w_part = (const float*)d_in[2];
    const float* b_part = (const float*)d_in[3];
    const float* gw     = (const float*)d_in[4];
    float* out = (float*)d_out;
    float* out_tail = out + KK * OO;   // coarsen_adj region

    zero_kernel<<<(NN * OO + 255) / 256, 256>>>(out_tail);
    assign_kernel<<<NN / 8, 256>>>(x, w_part, b_part);
    build_lists_kernel<<<1, 32>>>();
    coarsen_kernel<<<NN / 8, 256>>>(adj, out_tail);
    gcn_kernel<<<dim3(NN / 16, KK), 256>>>(x, adj, gw);
    bn_stats_kernel<<<NN / 32, 256>>>();
    final_kernel<<<KK, 256>>>(out);
}

// round 2
// speedup vs baseline: 1.6487x; 1.6487x over previous
#include <cuda_runtime.h>

#define NN 2048
#define KK 16
#define FF 256
#define OO 256

// ---- scratch (static device memory; no allocation) ----
__device__ unsigned int g_mask[NN];
__device__ int   g_list[KK * NN];
__device__ int   g_cnt[KK];
__device__ float g_h[NN * OO];
__device__ float g_colsum[OO];
__device__ float g_colsumsq[OO];

// ---------------------------------------------------------------
// 0) zero scratch + coarsen region of output
// ---------------------------------------------------------------
__global__ void zero_kernel(float* __restrict__ out_tail) {
    int idx = blockIdx.x * blockDim.x + threadIdx.x;
    if (idx < NN * OO) g_h[idx] = 0.f;
    if (idx < OO) { g_colsum[idx] = 0.f; g_colsumsq[idx] = 0.f; }
    if (idx < KK * KK) out_tail[idx] = 0.f;
}

// ---------------------------------------------------------------
// 1) per-node hard assignment mask: relu(x@W+b) == rowmax (ties kept)
//    one warp per node
// ---------------------------------------------------------------
__global__ void assign_kernel(const float* __restrict__ x,
                              const float* __restrict__ w,
                              const float* __restrict__ b) {
    int node = (blockIdx.x * blockDim.x + threadIdx.x) >> 5;
    int lane = threadIdx.x & 31;
    if (node >= NN) return;
    float p[KK];
#pragma unroll
    for (int k = 0; k < KK; k++) p[k] = 0.f;
    const float* xr = x + node * FF;
    for (int f = lane; f < FF; f += 32) {
        float xv = xr[f];
        const float* wr = w + f * KK;
#pragma unroll
        for (int k = 0; k < KK; k++) p[k] += xv * wr[k];
    }
#pragma unroll
    for (int k = 0; k < KK; k++) {
#pragma unroll
        for (int off = 16; off >= 1; off >>= 1)
            p[k] += __shfl_xor_sync(0xffffffffu, p[k], off);
    }
    if (lane == 0) {
        float m = 0.f;
#pragma unroll
        for (int k = 0; k < KK; k++) {
            p[k] = fmaxf(p[k] + b[k], 0.f);
            m = fmaxf(m, p[k]);
        }
        unsigned mask = 0u;
#pragma unroll
        for (int k = 0; k < KK; k++)
            if (p[k] == m) mask |= (1u << k);
        g_mask[node] = mask;
    }
}

// ---------------------------------------------------------------
// 2) deterministic parallel list build: single block of 1024 threads.
//    32 warps ballot 64 chunks of 32 nodes; 16 threads prefix-sum;
//    warps write compacted positions.
// ---------------------------------------------------------------
__global__ void __launch_bounds__(1024) build_lists_kernel() {
    __shared__ unsigned bal_sh[64][KK];
    __shared__ int      off_sh[64][KK];
    int tid = threadIdx.x, warp = tid >> 5, lane = tid & 31;

    for (int c = warp; c < 64; c += 32) {
        unsigned m = g_mask[c * 32 + lane];
#pragma unroll
        for (int k = 0; k < KK; k++) {
            unsigned bal = __ballot_sync(0xffffffffu, (m >> k) & 1u);
            if (lane == k) bal_sh[c][k] = bal;
        }
    }
    __syncthreads();
    if (tid < KK) {
        int s = 0;
        for (int c = 0; c < 64; c++) {
            off_sh[c][tid] = s;
            s += __popc(bal_sh[c][tid]);
        }
        g_cnt[tid] = s;
    }
    __syncthreads();
    for (int c = warp; c < 64; c += 32) {
#pragma unroll
        for (int k = 0; k < KK; k++) {
            unsigned bal = bal_sh[c][k];
            if ((bal >> lane) & 1u)
                g_list[k * NN + off_sh[c][k] + __popc(bal & ((1u << lane) - 1u))]
                    = c * 32 + lane;
        }
    }
}

// ---------------------------------------------------------------
// 3) coarsen_adj: warp per row, float4 adj loads, uint4 mask loads,
//    block-level smem aggregation, one global atomic/entry/block.
// ---------------------------------------------------------------
__global__ void __launch_bounds__(256) coarsen_kernel(const float* __restrict__ adj,
                                                      float* __restrict__ out_tail) {
    __shared__ __align__(16) unsigned mask_sh[NN];
    __shared__ float acc_sh[KK * KK];
    int tid = threadIdx.x;
    if (tid < KK * KK) acc_sh[tid] = 0.f;
    for (int i = tid; i < NN; i += 256) mask_sh[i] = g_mask[i];
    __syncthreads();

    int w = tid >> 5, lane = tid & 31;
    int row = blockIdx.x * 8 + w;
    float c[KK];
#pragma unroll
    for (int k = 0; k < KK; k++) c[k] = 0.f;

    const float4* arow = (const float4*)(adj + (size_t)row * NN);
    const uint4*  mrow = (const uint4*)mask_sh;
#pragma unroll 4
    for (int q = lane; q < NN / 4; q += 32) {
        float4 a = arow[q];
        uint4  m = mrow[q];
#pragma unroll
        for (int k = 0; k < KK; k++) {
            unsigned bit = 1u << k;
            if (m.x & bit) c[k] += a.x;
            if (m.y & bit) c[k] += a.y;
            if (m.z & bit) c[k] += a.z;
            if (m.w & bit) c[k] += a.w;
        }
    }
#pragma unroll
    for (int k = 0; k < KK; k++) {
#pragma unroll
        for (int off = 16; off >= 1; off >>= 1)
            c[k] += __shfl_xor_sync(0xffffffffu, c[k], off);
    }
    if (lane == 0) {
        unsigned mi = mask_sh[row];
        while (mi) {
            int a = __ffs(mi) - 1;
            mi &= mi - 1;
#pragma unroll
            for (int bcol = 0; bcol < KK; bcol++)
                atomicAdd(&acc_sh[a * KK + bcol], c[bcol]);
        }
    }
    __syncthreads();
    if (tid < KK * KK) {
        float v = acc_sh[tid];
        if (v != 0.f) atomicAdd(&out_tail[tid], v);
    }
}

// ---------------------------------------------------------------
// 4) GCN per-group: 16-node tile per block, float4 shared reads.
//    V = A_sub @ X_sub + 2*X ; Z = V @ W_k ; L2-normalize; add into h.
// ---------------------------------------------------------------
__global__ void __launch_bounds__(256) gcn_kernel(const float* __restrict__ x,
                                                  const float* __restrict__ adj,
                                                  const float* __restrict__ gw) {
    int k = blockIdx.y;
    int n = g_cnt[k];
    int t0 = blockIdx.x * 16;
    if (t0 >= n) return;

    __shared__ __align__(16) int   list_sh[NN + 64];
    __shared__ __align__(16) float a_sh[16][68];
    __shared__ __align__(16) float v_sh[16][260];
    __shared__ float red_sh[16][8];
    __shared__ float inv_sh[16];

    int tid = threadIdx.x;
    int nn = (n + 63) & ~63;
    for (int i = tid; i < nn; i += 256) list_sh[i] = (i < n) ? g_list[k * NN + i] : 0;
    __syncthreads();

    int rows = n - t0; if (rows > 16) rows = 16;
    int irow[16];
#pragma unroll
    for (int r = 0; r < 16; r++) irow[r] = list_sh[t0 + (r < rows ? r : 0)];

    const int f = tid;  // feature / output column index, 0..255
    float acc[16];
#pragma unroll
    for (int r = 0; r < 16; r++) acc[r] = 2.f * x[(size_t)irow[r] * FF + f];

    // stage 1: acc[r] += sum_{j in group} adj[irow[r], j] * x[j, f]
    for (int j0 = 0; j0 < n; j0 += 64) {
        int cmax = n - j0; if (cmax > 64) cmax = 64;
        for (int e = tid; e < 16 * 64; e += 256) {
            int r = e >> 6, c = e & 63;
            float a = 0.f;
            if (c < cmax) {
                int rr = (r < rows) ? r : 0;
                a = adj[(size_t)list_sh[t0 + rr] * NN + list_sh[j0 + c]];
            }
            a_sh[r][c] = a;
        }
        __syncthreads();
#pragma unroll 2
        for (int c = 0; c < 64; c += 4) {
            float xv0 = x[(size_t)list_sh[j0 + c + 0] * FF + f];
            float xv1 = x[(size_t)list_sh[j0 + c + 1] * FF + f];
            float xv2 = x[(size_t)list_sh[j0 + c + 2] * FF + f];
            float xv3 = x[(size_t)list_sh[j0 + c + 3] * FF + f];
#pragma unroll
            for (int r = 0; r < 16; r++) {
                float4 a4 = *(const float4*)&a_sh[r][c];
                acc[r] += a4.x * xv0;
                acc[r] += a4.y * xv1;
                acc[r] += a4.z * xv2;
                acc[r] += a4.w * xv3;
            }
        }
        __syncthreads();
    }

#pragma unroll
    for (int r = 0; r < 16; r++) v_sh[r][f] = acc[r];
    __syncthreads();

    // stage 2: Z[r][f] = sum_ff V[r][ff] * W_k[ff][f]
    float z[16];
#pragma unroll
    for (int r = 0; r < 16; r++) z[r] = 0.f;
    const float* Wk = gw + (size_t)k * FF * OO + f;
#pragma unroll 2
    for (int ff = 0; ff < FF; ff += 4) {
        float w0 = Wk[(size_t)(ff + 0) * OO];
        float w1 = Wk[(size_t)(ff + 1) * OO];
        float w2 = Wk[(size_t)(ff + 2) * OO];
        float w3 = Wk[(size_t)(ff + 3) * OO];
#pragma unroll
        for (int r = 0; r < 16; r++) {
            float4 v4 = *(const float4*)&v_sh[r][ff];
            z[r] += v4.x * w0;
            z[r] += v4.y * w1;
            z[r] += v4.z * w2;
            z[r] += v4.w * w3;
        }
    }

    // per-row L2 norm across 256 threads
    int lane = tid & 31, wrp = tid >> 5;
#pragma unroll
    for (int r = 0; r < 16; r++) {
        float v = z[r] * z[r];
#pragma unroll
        for (int off = 16; off >= 1; off >>= 1)
            v += __shfl_xor_sync(0xffffffffu, v, off);
        if (lane == 0) red_sh[r][wrp] = v;
    }
    __syncthreads();
    if (tid < 16) {
        float s = 0.f;
#pragma unroll
        for (int ww = 0; ww < 8; ww++) s += red_sh[tid][ww];
        inv_sh[tid] = 1.f / fmaxf(sqrtf(s), 1e-12f);
    }
    __syncthreads();

#pragma unroll
    for (int r = 0; r < 16; r++)
        if (r < rows)
            atomicAdd(&g_h[(size_t)irow[r] * OO + f], z[r] * inv_sh[r]);
}

// ---------------------------------------------------------------
// 5) BN column statistics over relu(h)
// ---------------------------------------------------------------
__global__ void bn_stats_kernel() {
    int o = threadIdx.x;
    int r0 = blockIdx.x * 32;
    float s = 0.f, s2 = 0.f;
#pragma unroll 4
    for (int r = 0; r < 32; r++) {
        float v = fmaxf(g_h[(size_t)(r0 + r) * OO + o], 0.f);
        s += v; s2 += v * v;
    }
    atomicAdd(&g_colsum[o], s);
    atomicAdd(&g_colsumsq[o], s2);
}

// ---------------------------------------------------------------
// 6) apply BN and pool: out[a][o] = sum_{i in group a} h_bn[i][o]
// ---------------------------------------------------------------
__global__ void final_kernel(float* __restrict__ out) {
    int a = blockIdx.x;
    int o = threadIdx.x;
    const float invN = 1.f / (float)NN;
    float mean = g_colsum[o] * invN;
    float var  = g_colsumsq[o] * invN - mean * mean;
    float inv  = 1.f / sqrtf(var + 1e-5f);
    int n = g_cnt[a];
    float accv = 0.f;
    int t = 0;
    for (; t + 4 <= n; t += 4) {
        int i0 = g_list[a * NN + t + 0];
        int i1 = g_list[a * NN + t + 1];
        int i2 = g_list[a * NN + t + 2];
        int i3 = g_list[a * NN + t + 3];
        accv += fmaxf(g_h[(size_t)i0 * OO + o], 0.f);
        accv += fmaxf(g_h[(size_t)i1 * OO + o], 0.f);
        accv += fmaxf(g_h[(size_t)i2 * OO + o], 0.f);
        accv += fmaxf(g_h[(size_t)i3 * OO + o], 0.f);
    }
    for (; t < n; t++) {
        int i = g_list[a * NN + t];
        accv += fmaxf(g_h[(size_t)i * OO + o], 0.f);
    }
    // sum over members of (relu(h)-mean)*inv == (sum relu(h) - n*mean)*inv
    out[a * OO + o] = (accv - (float)n * mean) * inv;
}

// ---------------------------------------------------------------
extern "C" void kernel_launch(void* const* d_in, const int* in_sizes, int n_in,
                              void* d_out, int out_size) {
    const float* x      = (const float*)d_in[0];
    const float* adj    = (const float*)d_in[1];
    const float* w_part = (const float*)d_in[2];
    const float* b_part = (const float*)d_in[3];
    const float* gw     = (const float*)d_in[4];
    float* out = (float*)d_out;
    float* out_tail = out + KK * OO;   // coarsen_adj region

    zero_kernel<<<(NN * OO + 255) / 256, 256>>>(out_tail);
    assign_kernel<<<NN / 8, 256>>>(x, w_part, b_part);
    build_lists_kernel<<<1, 1024>>>();
    coarsen_kernel<<<NN / 8, 256>>>(adj, out_tail);
    gcn_kernel<<<dim3(NN / 16, KK), 256>>>(x, adj, gw);
    bn_stats_kernel<<<NN / 32, 256>>>();
    final_kernel<<<KK, 256>>>(out);
}

// round 3
// speedup vs baseline: 1.7861x; 1.0833x over previous
#include <cuda_runtime.h>

#define NN 2048
#define KK 16
#define FF 256
#define OO 256

// ---- scratch (static device memory; no allocation) ----
__device__ unsigned int g_mask[NN];
__device__ int   g_list[KK * NN];
__device__ int   g_cnt[KK];
__device__ float g_h[NN * OO];
__device__ float g_colsum[OO];
__device__ float g_colsumsq[OO];
__device__ float g_U[KK * NN];   // U[b][j] = sum_{i in b} adj[i][j]

// ---------------------------------------------------------------
// 1) per-node hard assignment mask + fused zeroing of scratch
//    one warp per node; grid 256 x 256 threads
// ---------------------------------------------------------------
__global__ void __launch_bounds__(256) assign_kernel(const float* __restrict__ x,
                                                     const float* __restrict__ w,
                                                     const float* __restrict__ b) {
    // fused zero of g_h / colsum / colsumsq (65536 threads, 8 floats each)
    int gt = blockIdx.x * 256 + threadIdx.x;
#pragma unroll
    for (int r = 0; r < 8; r++) g_h[gt + r * 65536] = 0.f;
    if (gt < OO) { g_colsum[gt] = 0.f; g_colsumsq[gt] = 0.f; }

    int node = gt >> 5;
    int lane = threadIdx.x & 31;
    float p[KK];
#pragma unroll
    for (int k = 0; k < KK; k++) p[k] = 0.f;
    const float* xr = x + node * FF;
    for (int f = lane; f < FF; f += 32) {
        float xv = xr[f];
        const float* wr = w + f * KK;
#pragma unroll
        for (int k = 0; k < KK; k++) p[k] += xv * wr[k];
    }
#pragma unroll
    for (int k = 0; k < KK; k++) {
#pragma unroll
        for (int off = 16; off >= 1; off >>= 1)
            p[k] += __shfl_xor_sync(0xffffffffu, p[k], off);
    }
    if (lane == 0) {
        float m = 0.f;
#pragma unroll
        for (int k = 0; k < KK; k++) {
            p[k] = fmaxf(p[k] + b[k], 0.f);
            m = fmaxf(m, p[k]);
        }
        unsigned mask = 0u;
#pragma unroll
        for (int k = 0; k < KK; k++)
            if (p[k] == m) mask |= (1u << k);
        g_mask[node] = mask;
    }
}

// ---------------------------------------------------------------
// 2) deterministic parallel list build (single 1024-thread block)
// ---------------------------------------------------------------
__global__ void __launch_bounds__(1024) build_lists_kernel() {
    __shared__ unsigned bal_sh[64][KK];
    __shared__ int      off_sh[64][KK];
    int tid = threadIdx.x, warp = tid >> 5, lane = tid & 31;

    for (int c = warp; c < 64; c += 32) {
        unsigned m = g_mask[c * 32 + lane];
#pragma unroll
        for (int k = 0; k < KK; k++) {
            unsigned bal = __ballot_sync(0xffffffffu, (m >> k) & 1u);
            if (lane == k) bal_sh[c][k] = bal;
        }
    }
    __syncthreads();
    if (tid < KK) {
        int s = 0;
        for (int c = 0; c < 64; c++) {
            off_sh[c][tid] = s;
            s += __popc(bal_sh[c][tid]);
        }
        g_cnt[tid] = s;
    }
    __syncthreads();
    for (int c = warp; c < 64; c += 32) {
#pragma unroll
        for (int k = 0; k < KK; k++) {
            unsigned bal = bal_sh[c][k];
            if ((bal >> lane) & 1u)
                g_list[k * NN + off_sh[c][k] + __popc(bal & ((1u << lane) - 1u))]
                    = c * 32 + lane;
        }
    }
}

// ---------------------------------------------------------------
// 3) U[b][j] = sum_{i in list_b} adj[i][j]  — bucket-free streaming pass.
//    grid (8 j-chunks, 16 buckets), 256 threads; 1 LDG + 1 FADD / element.
// ---------------------------------------------------------------
__global__ void __launch_bounds__(256) coarsenU_kernel(const float* __restrict__ adj) {
    int bkt = blockIdx.y;
    int j = blockIdx.x * 256 + threadIdx.x;
    __shared__ int list_sh[NN];
    int n = g_cnt[bkt];
    for (int i = threadIdx.x; i < n; i += 256) list_sh[i] = g_list[bkt * NN + i];
    __syncthreads();

    float a0 = 0.f, a1 = 0.f, a2 = 0.f, a3 = 0.f;
    float a4 = 0.f, a5 = 0.f, a6 = 0.f, a7 = 0.f;
    int t = 0;
    for (; t + 8 <= n; t += 8) {
        a0 += adj[(size_t)list_sh[t + 0] * NN + j];
        a1 += adj[(size_t)list_sh[t + 1] * NN + j];
        a2 += adj[(size_t)list_sh[t + 2] * NN + j];
        a3 += adj[(size_t)list_sh[t + 3] * NN + j];
        a4 += adj[(size_t)list_sh[t + 4] * NN + j];
        a5 += adj[(size_t)list_sh[t + 5] * NN + j];
        a6 += adj[(size_t)list_sh[t + 6] * NN + j];
        a7 += adj[(size_t)list_sh[t + 7] * NN + j];
    }
    for (; t < n; t++) a0 += adj[(size_t)list_sh[t] * NN + j];
    g_U[bkt * NN + j] = ((a0 + a1) + (a2 + a3)) + ((a4 + a5) + (a6 + a7));
}

// ---------------------------------------------------------------
// 4) GCN per-group: 16-node tile per block, float4 shared reads.
// ---------------------------------------------------------------
__global__ void __launch_bounds__(256) gcn_kernel(const float* __restrict__ x,
                                                  const float* __restrict__ adj,
                                                  const float* __restrict__ gw) {
    int k = blockIdx.y;
    int n = g_cnt[k];
    int t0 = blockIdx.x * 16;
    if (t0 >= n) return;

    __shared__ __align__(16) int   list_sh[NN + 64];
    __shared__ __align__(16) float a_sh[16][68];
    __shared__ __align__(16) float v_sh[16][260];
    __shared__ float red_sh[16][8];
    __shared__ float inv_sh[16];

    int tid = threadIdx.x;
    int nn = (n + 63) & ~63;
    for (int i = tid; i < nn; i += 256) list_sh[i] = (i < n) ? g_list[k * NN + i] : 0;
    __syncthreads();

    int rows = n - t0; if (rows > 16) rows = 16;
    int irow[16];
#pragma unroll
    for (int r = 0; r < 16; r++) irow[r] = list_sh[t0 + (r < rows ? r : 0)];

    const int f = tid;
    float acc[16];
#pragma unroll
    for (int r = 0; r < 16; r++) acc[r] = 2.f * x[(size_t)irow[r] * FF + f];

    for (int j0 = 0; j0 < n; j0 += 64) {
        int cmax = n - j0; if (cmax > 64) cmax = 64;
        for (int e = tid; e < 16 * 64; e += 256) {
            int r = e >> 6, c = e & 63;
            float a = 0.f;
            if (c < cmax) {
                int rr = (r < rows) ? r : 0;
                a = adj[(size_t)list_sh[t0 + rr] * NN + list_sh[j0 + c]];
            }
            a_sh[r][c] = a;
        }
        __syncthreads();
#pragma unroll 2
        for (int c = 0; c < 64; c += 4) {
            float xv0 = x[(size_t)list_sh[j0 + c + 0] * FF + f];
            float xv1 = x[(size_t)list_sh[j0 + c + 1] * FF + f];
            float xv2 = x[(size_t)list_sh[j0 + c + 2] * FF + f];
            float xv3 = x[(size_t)list_sh[j0 + c + 3] * FF + f];
#pragma unroll
            for (int r = 0; r < 16; r++) {
                float4 a4 = *(const float4*)&a_sh[r][c];
                acc[r] += a4.x * xv0;
                acc[r] += a4.y * xv1;
                acc[r] += a4.z * xv2;
                acc[r] += a4.w * xv3;
            }
        }
        __syncthreads();
    }

#pragma unroll
    for (int r = 0; r < 16; r++) v_sh[r][f] = acc[r];
    __syncthreads();

    float z[16];
#pragma unroll
    for (int r = 0; r < 16; r++) z[r] = 0.f;
    const float* Wk = gw + (size_t)k * FF * OO + f;
#pragma unroll 2
    for (int ff = 0; ff < FF; ff += 4) {
        float w0 = Wk[(size_t)(ff + 0) * OO];
        float w1 = Wk[(size_t)(ff + 1) * OO];
        float w2 = Wk[(size_t)(ff + 2) * OO];
        float w3 = Wk[(size_t)(ff + 3) * OO];
#pragma unroll
        for (int r = 0; r < 16; r++) {
            float4 v4 = *(const float4*)&v_sh[r][ff];
            z[r] += v4.x * w0;
            z[r] += v4.y * w1;
            z[r] += v4.z * w2;
            z[r] += v4.w * w3;
        }
    }

    int lane = tid & 31, wrp = tid >> 5;
#pragma unroll
    for (int r = 0; r < 16; r++) {
        float v = z[r] * z[r];
#pragma unroll
        for (int off = 16; off >= 1; off >>= 1)
            v += __shfl_xor_sync(0xffffffffu, v, off);
        if (lane == 0) red_sh[r][wrp] = v;
    }
    __syncthreads();
    if (tid < 16) {
        float s = 0.f;
#pragma unroll
        for (int ww = 0; ww < 8; ww++) s += red_sh[tid][ww];
        inv_sh[tid] = 1.f / fmaxf(sqrtf(s), 1e-12f);
    }
    __syncthreads();

#pragma unroll
    for (int r = 0; r < 16; r++)
        if (r < rows)
            atomicAdd(&g_h[(size_t)irow[r] * OO + f], z[r] * inv_sh[r]);
}

// ---------------------------------------------------------------
// 5) BN column statistics over relu(h)
// ---------------------------------------------------------------
__global__ void __launch_bounds__(256) bn_stats_kernel() {
    int o = threadIdx.x;
    int r0 = blockIdx.x * 32;
    float s = 0.f, s2 = 0.f;
#pragma unroll 8
    for (int r = 0; r < 32; r++) {
        float v = fmaxf(g_h[(size_t)(r0 + r) * OO + o], 0.f);
        s += v; s2 += v * v;
    }
    atomicAdd(&g_colsum[o], s);
    atomicAdd(&g_colsumsq[o], s2);
}

// ---------------------------------------------------------------
// 6) final: BN-apply + pool, plus coarsen_adj reduction from U.
//    block a: out[a][o] and coarsen[b][a] for all b.
// ---------------------------------------------------------------
__global__ void __launch_bounds__(256) final_kernel(float* __restrict__ out) {
    int a = blockIdx.x;
    int o = threadIdx.x;
    __shared__ int list_sh[NN];
    __shared__ float csh[KK][KK + 1];
    int n = g_cnt[a];
    for (int i = o; i < n; i += 256) list_sh[i] = g_list[a * NN + i];
    __syncthreads();

    // --- BN pool ---
    const float invN = 1.f / (float)NN;
    float mean = g_colsum[o] * invN;
    float var  = g_colsumsq[o] * invN - mean * mean;
    float inv  = rsqrtf(var + 1e-5f);
    float accv = 0.f;
    int t = 0;
    for (; t + 4 <= n; t += 4) {
        accv += fmaxf(g_h[(size_t)list_sh[t + 0] * OO + o], 0.f);
        accv += fmaxf(g_h[(size_t)list_sh[t + 1] * OO + o], 0.f);
        accv += fmaxf(g_h[(size_t)list_sh[t + 2] * OO + o], 0.f);
        accv += fmaxf(g_h[(size_t)list_sh[t + 3] * OO + o], 0.f);
    }
    for (; t < n; t++)
        accv += fmaxf(g_h[(size_t)list_sh[t] * OO + o], 0.f);
    out[a * OO + o] = (accv - (float)n * mean) * inv;

    // --- coarsen[b][a] = sum_{j in list_a} U[b][j] ---
    int b = o >> 4, p = o & 15;
    float cpart = 0.f;
    for (int tt = p; tt < n; tt += 16)
        cpart += g_U[b * NN + list_sh[tt]];
    csh[b][p] = cpart;
    __syncthreads();
    if (o < KK) {
        float s = 0.f;
#pragma unroll
        for (int pp = 0; pp < KK; pp++) s += csh[o][pp];
        out[KK * OO + o * KK + a] = s;
    }
}

// ---------------------------------------------------------------
extern "C" void kernel_launch(void* const* d_in, const int* in_sizes, int n_in,
                              void* d_out, int out_size) {
    const float* x      = (const float*)d_in[0];
    const float* adj    = (const float*)d_in[1];
    const float* w_part = (const float*)d_in[2];
    const float* b_part = (const float*)d_in[3];
    const float* gw     = (const float*)d_in[4];
    float* out = (float*)d_out;

    assign_kernel<<<NN / 8, 256>>>(x, w_part, b_part);
    build_lists_kernel<<<1, 1024>>>();
    coarsenU_kernel<<<dim3(8, KK), 256>>>(adj);
    gcn_kernel<<<dim3(NN / 16, KK), 256>>>(x, adj, gw);
    bn_stats_kernel<<<NN / 32, 256>>>();
    final_kernel<<<KK, 256>>>(out);
}

// round 4
// speedup vs baseline: 1.9478x; 1.0905x over previous
#include <cuda_runtime.h>

#define NN 2048
#define KK 16
#define FF 256
#define OO 256
#define RT 8   // gcn row tile

// ---- scratch (static device memory; no allocation) ----
__device__ unsigned int g_mask[NN];
__device__ int   g_list[KK * NN];
__device__ int   g_cnt[KK];
__device__ float g_h[NN * OO];
__device__ float g_colsum[OO];
__device__ float g_colsumsq[OO];
__device__ float g_U[KK * NN];   // U[b][j] = sum_{i in b} adj[i][j]

// ---------------------------------------------------------------
// 1) per-node hard assignment mask + fused zeroing of scratch
// ---------------------------------------------------------------
__global__ void __launch_bounds__(256) assign_kernel(const float* __restrict__ x,
                                                     const float* __restrict__ w,
                                                     const float* __restrict__ b) {
    int gt = blockIdx.x * 256 + threadIdx.x;
#pragma unroll
    for (int r = 0; r < 8; r++) g_h[gt + r * 65536] = 0.f;
    if (gt < OO) { g_colsum[gt] = 0.f; g_colsumsq[gt] = 0.f; }

    int node = gt >> 5;
    int lane = threadIdx.x & 31;
    float p[KK];
#pragma unroll
    for (int k = 0; k < KK; k++) p[k] = 0.f;
    const float* xr = x + node * FF;
    for (int f = lane; f < FF; f += 32) {
        float xv = xr[f];
        const float* wr = w + f * KK;
#pragma unroll
        for (int k = 0; k < KK; k++) p[k] += xv * wr[k];
    }
#pragma unroll
    for (int k = 0; k < KK; k++) {
#pragma unroll
        for (int off = 16; off >= 1; off >>= 1)
            p[k] += __shfl_xor_sync(0xffffffffu, p[k], off);
    }
    if (lane == 0) {
        float m = 0.f;
#pragma unroll
        for (int k = 0; k < KK; k++) {
            p[k] = fmaxf(p[k] + b[k], 0.f);
            m = fmaxf(m, p[k]);
        }
        unsigned mask = 0u;
#pragma unroll
        for (int k = 0; k < KK; k++)
            if (p[k] == m) mask |= (1u << k);
        g_mask[node] = mask;
    }
}

// ---------------------------------------------------------------
// 2) deterministic parallel list build (single 1024-thread block)
// ---------------------------------------------------------------
__global__ void __launch_bounds__(1024) build_lists_kernel() {
    __shared__ unsigned bal_sh[64][KK];
    __shared__ int      off_sh[64][KK];
    int tid = threadIdx.x, warp = tid >> 5, lane = tid & 31;

    for (int c = warp; c < 64; c += 32) {
        unsigned m = g_mask[c * 32 + lane];
#pragma unroll
        for (int k = 0; k < KK; k++) {
            unsigned bal = __ballot_sync(0xffffffffu, (m >> k) & 1u);
            if (lane == k) bal_sh[c][k] = bal;
        }
    }
    __syncthreads();
    if (tid < KK) {
        int s = 0;
        for (int c = 0; c < 64; c++) {
            off_sh[c][tid] = s;
            s += __popc(bal_sh[c][tid]);
        }
        g_cnt[tid] = s;
    }
    __syncthreads();
    for (int c = warp; c < 64; c += 32) {
#pragma unroll
        for (int k = 0; k < KK; k++) {
            unsigned bal = bal_sh[c][k];
            if ((bal >> lane) & 1u)
                g_list[k * NN + off_sh[c][k] + __popc(bal & ((1u << lane) - 1u))]
                    = c * 32 + lane;
        }
    }
}

// ---------------------------------------------------------------
// 3) U[b][j] = sum_{i in list_b} adj[i][j]
// ---------------------------------------------------------------
__global__ void __launch_bounds__(256) coarsenU_kernel(const float* __restrict__ adj) {
    int bkt = blockIdx.y;
    int j = blockIdx.x * 256 + threadIdx.x;
    __shared__ int list_sh[NN];
    int n = g_cnt[bkt];
    for (int i = threadIdx.x; i < n; i += 256) list_sh[i] = g_list[bkt * NN + i];
    __syncthreads();

    float a0 = 0.f, a1 = 0.f, a2 = 0.f, a3 = 0.f;
    float a4 = 0.f, a5 = 0.f, a6 = 0.f, a7 = 0.f;
    int t = 0;
    for (; t + 8 <= n; t += 8) {
        a0 += adj[(size_t)list_sh[t + 0] * NN + j];
        a1 += adj[(size_t)list_sh[t + 1] * NN + j];
        a2 += adj[(size_t)list_sh[t + 2] * NN + j];
        a3 += adj[(size_t)list_sh[t + 3] * NN + j];
        a4 += adj[(size_t)list_sh[t + 4] * NN + j];
        a5 += adj[(size_t)list_sh[t + 5] * NN + j];
        a6 += adj[(size_t)list_sh[t + 6] * NN + j];
        a7 += adj[(size_t)list_sh[t + 7] * NN + j];
    }
    for (; t < n; t++) a0 += adj[(size_t)list_sh[t] * NN + j];
    g_U[bkt * NN + j] = ((a0 + a1) + (a2 + a3)) + ((a4 + a5) + (a6 + a7));
}

// ---------------------------------------------------------------
// 4) GCN per-group: RT-node tile per block (RT=8 for concurrency).
//    V = A_sub @ X_sub + 2*X ; Z = V @ W_k ; L2-normalize; add into h.
// ---------------------------------------------------------------
__global__ void __launch_bounds__(256) gcn_kernel(const float* __restrict__ x,
                                                  const float* __restrict__ adj,
                                                  const float* __restrict__ gw) {
    int k = blockIdx.y;
    int n = g_cnt[k];
    int t0 = blockIdx.x * RT;
    if (t0 >= n) return;

    __shared__ __align__(16) int   list_sh[NN + 64];
    __shared__ __align__(16) float a_sh[RT][68];
    __shared__ __align__(16) float v_sh[RT][260];
    __shared__ float red_sh[RT][8];
    __shared__ float inv_sh[RT];

    int tid = threadIdx.x;
    int nn = (n + 63) & ~63;
    for (int i = tid; i < nn; i += 256) list_sh[i] = (i < n) ? g_list[k * NN + i] : 0;
    __syncthreads();

    int rows = n - t0; if (rows > RT) rows = RT;
    int irow[RT];
#pragma unroll
    for (int r = 0; r < RT; r++) irow[r] = list_sh[t0 + (r < rows ? r : 0)];

    const int f = tid;
    float acc[RT];
#pragma unroll
    for (int r = 0; r < RT; r++) acc[r] = 2.f * x[(size_t)irow[r] * FF + f];

    // stage 1: acc[r] += sum_{j in group} adj[irow[r], j] * x[j, f]
    for (int j0 = 0; j0 < n; j0 += 64) {
        int cmax = n - j0; if (cmax > 64) cmax = 64;
        for (int e = tid; e < RT * 64; e += 256) {
            int r = e >> 6, c = e & 63;
            float a = 0.f;
            if (c < cmax) {
                int rr = (r < rows) ? r : 0;
                a = adj[(size_t)list_sh[t0 + rr] * NN + list_sh[j0 + c]];
            }
            a_sh[r][c] = a;
        }
        __syncthreads();
#pragma unroll 4
        for (int c = 0; c < 64; c += 4) {
            float xv0 = x[(size_t)list_sh[j0 + c + 0] * FF + f];
            float xv1 = x[(size_t)list_sh[j0 + c + 1] * FF + f];
            float xv2 = x[(size_t)list_sh[j0 + c + 2] * FF + f];
            float xv3 = x[(size_t)list_sh[j0 + c + 3] * FF + f];
#pragma unroll
            for (int r = 0; r < RT; r++) {
                float4 a4 = *(const float4*)&a_sh[r][c];
                acc[r] += a4.x * xv0;
                acc[r] += a4.y * xv1;
                acc[r] += a4.z * xv2;
                acc[r] += a4.w * xv3;
            }
        }
        __syncthreads();
    }

#pragma unroll
    for (int r = 0; r < RT; r++) v_sh[r][f] = acc[r];
    __syncthreads();

    // stage 2: Z[r][f] = sum_ff V[r][ff] * W_k[ff][f]
    float z[RT];
#pragma unroll
    for (int r = 0; r < RT; r++) z[r] = 0.f;
    const float* Wk = gw + (size_t)k * FF * OO + f;
#pragma unroll 4
    for (int ff = 0; ff < FF; ff += 4) {
        float w0 = Wk[(size_t)(ff + 0) * OO];
        float w1 = Wk[(size_t)(ff + 1) * OO];
        float w2 = Wk[(size_t)(ff + 2) * OO];
        float w3 = Wk[(size_t)(ff + 3) * OO];
#pragma unroll
        for (int r = 0; r < RT; r++) {
            float4 v4 = *(const float4*)&v_sh[r][ff];
            z[r] += v4.x * w0;
            z[r] += v4.y * w1;
            z[r] += v4.z * w2;
            z[r] += v4.w * w3;
        }
    }

    // per-row L2 norm across 256 threads
    int lane = tid & 31, wrp = tid >> 5;
#pragma unroll
    for (int r = 0; r < RT; r++) {
        float v = z[r] * z[r];
#pragma unroll
        for (int off = 16; off >= 1; off >>= 1)
            v += __shfl_xor_sync(0xffffffffu, v, off);
        if (lane == 0) red_sh[r][wrp] = v;
    }
    __syncthreads();
    if (tid < RT) {
        float s = 0.f;
#pragma unroll
        for (int ww = 0; ww < 8; ww++) s += red_sh[tid][ww];
        inv_sh[tid] = rsqrtf(fmaxf(s, 1e-24f));
    }
    __syncthreads();

#pragma unroll
    for (int r = 0; r < RT; r++)
        if (r < rows)
            atomicAdd(&g_h[(size_t)irow[r] * OO + f], z[r] * inv_sh[r]);
}

// ---------------------------------------------------------------
// 5) BN column statistics over relu(h)
// ---------------------------------------------------------------
__global__ void __launch_bounds__(256) bn_stats_kernel() {
    int o = threadIdx.x;
    int r0 = blockIdx.x * 32;
    float s = 0.f, s2 = 0.f;
#pragma unroll 8
    for (int r = 0; r < 32; r++) {
        float v = fmaxf(g_h[(size_t)(r0 + r) * OO + o], 0.f);
        s += v; s2 += v * v;
    }
    atomicAdd(&g_colsum[o], s);
    atomicAdd(&g_colsumsq[o], s2);
}

// ---------------------------------------------------------------
// 6) final: BN-apply + pool, plus coarsen_adj reduction from U.
// ---------------------------------------------------------------
__global__ void __launch_bounds__(256) final_kernel(float* __restrict__ out) {
    int a = blockIdx.x;
    int o = threadIdx.x;
    __shared__ int list_sh[NN];
    __shared__ float csh[KK][KK + 1];
    int n = g_cnt[a];
    for (int i = o; i < n; i += 256) list_sh[i] = g_list[a * NN + i];
    __syncthreads();

    const float invN = 1.f / (float)NN;
    float mean = g_colsum[o] * invN;
    float var  = g_colsumsq[o] * invN - mean * mean;
    float inv  = rsqrtf(var + 1e-5f);
    float accv = 0.f;
    int t = 0;
    for (; t + 4 <= n; t += 4) {
        accv += fmaxf(g_h[(size_t)list_sh[t + 0] * OO + o], 0.f);
        accv += fmaxf(g_h[(size_t)list_sh[t + 1] * OO + o], 0.f);
        accv += fmaxf(g_h[(size_t)list_sh[t + 2] * OO + o], 0.f);
        accv += fmaxf(g_h[(size_t)list_sh[t + 3] * OO + o], 0.f);
    }
    for (; t < n; t++)
        accv += fmaxf(g_h[(size_t)list_sh[t] * OO + o], 0.f);
    out[a * OO + o] = (accv - (float)n * mean) * inv;

    int b = o >> 4, p = o & 15;
    float cpart = 0.f;
    for (int tt = p; tt < n; tt += 16)
        cpart += g_U[b * NN + list_sh[tt]];
    csh[b][p] = cpart;
    __syncthreads();
    if (o < KK) {
        float s = 0.f;
#pragma unroll
        for (int pp = 0; pp < KK; pp++) s += csh[o][pp];
        out[KK * OO + o * KK + a] = s;
    }
}

// ---------------------------------------------------------------
extern "C" void kernel_launch(void* const* d_in, const int* in_sizes, int n_in,
                              void* d_out, int out_size) {
    const float* x      = (const float*)d_in[0];
    const float* adj    = (const float*)d_in[1];
    const float* w_part = (const float*)d_in[2];
    const float* b_part = (const float*)d_in[3];
    const float* gw     = (const float*)d_in[4];
    float* out = (float*)d_out;

    assign_kernel<<<NN / 8, 256>>>(x, w_part, b_part);
    build_lists_kernel<<<1, 1024>>>();
    coarsenU_kernel<<<dim3(8, KK), 256>>>(adj);
    gcn_kernel<<<dim3(NN / RT, KK), 256>>>(x, adj, gw);
    bn_stats_kernel<<<NN / 32, 256>>>();
    final_kernel<<<KK, 256>>>(out);
}